// round 1
// baseline (speedup 1.0000x reference)
#include <cuda_runtime.h>

#define DEV_INLINE __device__ __forceinline__

constexpr int cN   = 100000;   // nodes
constexpr int cE   = 1600000;  // edges
constexpr int cDIN = 32;       // node in channels
constexpr int cDE  = 16;       // edge feature dim
constexpr int cH   = 64;       // hidden
constexpr int cMH  = 128;      // mlp hidden
constexpr int cOUT = 10;       // out channels
constexpr int cG   = 128;      // graphs

// ---------------- scratch (device globals; no allocation allowed) ----------
__device__ __align__(16) float g_agg[cN * cH];
__device__ __align__(16) float g_h[cN * cH];
__device__ __align__(16) float g_x[cN * cH];
__device__ __align__(16) float g_sum[cH];
__device__ __align__(16) float g_sumsq[cH];
__device__ __align__(16) float g_pool[cG * cH];
__device__ __align__(16) int   g_cnt[cG];

DEV_INLINE void red_add_v4(float* p, float a, float b, float c, float d) {
    asm volatile("red.global.add.v4.f32 [%0], {%1,%2,%3,%4};"
                 :: "l"(p), "f"(a), "f"(b), "f"(c), "f"(d) : "memory");
}

// ---------------- zero scratch ---------------------------------------------
__global__ void __launch_bounds__(256) zero_kernel() {
    int i = blockIdx.x * 256 + threadIdx.x;
    float4 z4 = make_float4(0.f, 0.f, 0.f, 0.f);
    if (i < cN * cH / 4) ((float4*)g_agg)[i] = z4;
    if (i < cH / 4) { ((float4*)g_sum)[i] = z4; ((float4*)g_sumsq)[i] = z4; }
    if (i < cG * cH / 4) ((float4*)g_pool)[i] = z4;
    if (i < cG / 4) ((int4*)g_cnt)[i] = make_int4(0, 0, 0, 0);
}

// ---------------- edge message + scatter-add -------------------------------
// m = relu(x[src] + edge_attr @ ew^T + eb);  agg[dst] += m  (vector atomics)
// C/4 threads per edge, each handling 4 channels. ew kept transposed in smem
// ([k][c]) so the inner-product reads are conflict-free.
template <int C>
__global__ void __launch_bounds__(256) edge_kernel(
    const float* __restrict__ xin, int use_internal,
    const int* __restrict__ ei, const float* __restrict__ ea,
    const float* __restrict__ ew, const float* __restrict__ eb)
{
    constexpr int EPB = 1024 / C;  // edges per iteration (16 for C=64, 32 for C=32)
    constexpr int GP  = C / 4;     // threads per edge

    __shared__ float ew_t[cDE * C];
    __shared__ float eb_s[C];
    __shared__ float ea_s[EPB * cDE];
    __shared__ int   src_s[EPB], dst_s[EPB];

    const float* x = use_internal ? g_x : xin;
    int t = threadIdx.x;

    for (int i = t; i < cDE * C; i += 256) {
        int c = i >> 4, k = i & 15;
        ew_t[k * C + c] = ew[i];
    }
    for (int i = t; i < C; i += 256) eb_s[i] = eb[i];

    int el = t / GP;
    int c0 = (t % GP) * 4;

    for (int base = blockIdx.x * EPB; base < cE; base += gridDim.x * EPB) {
        __syncthreads();
        for (int i = t; i < EPB * cDE; i += 256) ea_s[i] = ea[base * cDE + i];
        if (t < EPB)            src_s[t]        = ei[base + t];
        else if (t < 2 * EPB)   dst_s[t - EPB]  = ei[cE + base + (t - EPB)];
        __syncthreads();

        const float* eap = &ea_s[el * cDE];
        float a0 = eb_s[c0], a1 = eb_s[c0 + 1], a2 = eb_s[c0 + 2], a3 = eb_s[c0 + 3];
        #pragma unroll
        for (int k = 0; k < cDE; k++) {
            float ev = eap[k];
            const float* wr = &ew_t[k * C + c0];
            a0 += wr[0] * ev; a1 += wr[1] * ev; a2 += wr[2] * ev; a3 += wr[3] * ev;
        }
        int s = src_s[el], d = dst_s[el];
        float4 xv = *(const float4*)(x + (size_t)s * C + c0);
        a0 = fmaxf(xv.x + a0, 0.f);
        a1 = fmaxf(xv.y + a1, 0.f);
        a2 = fmaxf(xv.z + a2, 0.f);
        a3 = fmaxf(xv.w + a3, 0.f);
        red_add_v4(&g_agg[(size_t)d * C + c0], a0, a1, a2, a3);
    }
}

// ---------------- node update: h2 = relu(relu((x+agg)W1^T+b1)W2^T+b2) ------
// Tile of 32 nodes per block; fused BN-stat partial sums.
template <int CIN>
__global__ void __launch_bounds__(256) node_kernel(
    const float* __restrict__ xin, int use_internal,
    const float* __restrict__ w1, const float* __restrict__ b1,
    const float* __restrict__ w2, const float* __restrict__ b2)
{
    __shared__ float u_s[32 * 65];   // input tile (reused for h2)
    __shared__ float w_s[cH * cH];   // W1 then W2
    __shared__ float h1_s[32 * 65];

    const float* x = use_internal ? g_x : xin;
    int t = threadIdx.x;
    int n0 = blockIdx.x * 32;

    for (int i = t; i < cH * CIN; i += 256) w_s[i] = w1[i];
    for (int i = t; i < 32 * CIN; i += 256) {
        int n = i / CIN, k = i % CIN;
        int node = n0 + n;
        u_s[n * 65 + k] = (node < cN)
            ? (x[(size_t)node * CIN + k] + g_agg[(size_t)node * CIN + k]) : 0.f;
    }
    __syncthreads();

    int n = t & 31, og = t >> 5;  // og in 0..7, 8 outputs each
    float acc[8];
    #pragma unroll
    for (int j = 0; j < 8; j++) acc[j] = b1[og * 8 + j];
    for (int k = 0; k < CIN; k++) {
        float uv = u_s[n * 65 + k];
        #pragma unroll
        for (int j = 0; j < 8; j++) acc[j] += uv * w_s[(og * 8 + j) * CIN + k];
    }
    #pragma unroll
    for (int j = 0; j < 8; j++) h1_s[n * 65 + og * 8 + j] = fmaxf(acc[j], 0.f);
    __syncthreads();

    for (int i = t; i < cH * cH; i += 256) w_s[i] = w2[i];
    __syncthreads();

    #pragma unroll
    for (int j = 0; j < 8; j++) acc[j] = b2[og * 8 + j];
    for (int k = 0; k < cH; k++) {
        float hv = h1_s[n * 65 + k];
        #pragma unroll
        for (int j = 0; j < 8; j++) acc[j] += hv * w_s[(og * 8 + j) * cH + k];
    }
    int node = n0 + n;
    #pragma unroll
    for (int j = 0; j < 8; j++) {
        float v = fmaxf(acc[j], 0.f);
        u_s[n * 65 + og * 8 + j] = v;
        if (node < cN) g_h[(size_t)node * cH + og * 8 + j] = v;
    }
    __syncthreads();

    // per-block BN partial sums (only valid nodes)
    if (t < cH) {
        int lim = min(32, cN - n0);
        float s = 0.f, s2 = 0.f;
        for (int nn = 0; nn < lim; nn++) {
            float v = u_s[nn * 65 + t];
            s += v; s2 += v * v;
        }
        atomicAdd(&g_sum[t], s);
        atomicAdd(&g_sumsq[t], s2);
    }
}

// ---------------- BN normalize (+ relu), optionally fused graph pooling ----
__global__ void __launch_bounds__(256) norm_kernel(
    const float* __restrict__ gamma, const float* __restrict__ beta,
    const int* __restrict__ batch, int last)
{
    int idx = blockIdx.x * 256 + threadIdx.x;
    if (idx >= cN * 16) return;
    int node = idx >> 4;
    int c0 = (idx & 15) * 4;
    float4 h = ((const float4*)g_h)[idx];
    float v[4] = {h.x, h.y, h.z, h.w};
    #pragma unroll
    for (int j = 0; j < 4; j++) {
        int c = c0 + j;
        float mu  = g_sum[c]   * (1.f / cN);
        float var = g_sumsq[c] * (1.f / cN) - mu * mu;
        float sc  = rsqrtf(var + 1e-5f) * gamma[c];
        v[j] = fmaxf((v[j] - mu) * sc + beta[c], 0.f);
    }
    ((float4*)g_x)[idx] = make_float4(v[0], v[1], v[2], v[3]);
    if (last) {
        int b = batch[node];
        red_add_v4(&g_pool[b * cH + c0], v[0], v[1], v[2], v[3]);
        if (c0 == 0) atomicAdd(&g_cnt[b], 1);
    }
}

// ---------------- pooled mean + MLP head -----------------------------------
__global__ void __launch_bounds__(128) head_kernel(
    const float* __restrict__ hw1, const float* __restrict__ hb1,
    const float* __restrict__ hw2, const float* __restrict__ hb2,
    float* __restrict__ out)
{
    __shared__ float p[cH], z[cMH];
    int g = blockIdx.x, t = threadIdx.x;
    if (t < cH) p[t] = g_pool[g * cH + t] / fmaxf((float)g_cnt[g], 1.f);
    __syncthreads();
    float acc = hb1[t];
    for (int c = 0; c < cH; c++) acc += p[c] * hw1[t * cH + c];
    z[t] = fmaxf(acc, 0.f);
    __syncthreads();
    if (t < cOUT) {
        float a = hb2[t];
        for (int m = 0; m < cMH; m++) a += z[m] * hw2[t * cMH + m];
        out[g * cOUT + t] = a;
    }
}

// ---------------- launch ----------------------------------------------------
extern "C" void kernel_launch(void* const* d_in, const int* in_sizes, int n_in,
                              void* d_out, int out_size)
{
    const float* x    = (const float*)d_in[0];
    const int*   ei   = (const int*)  d_in[1];
    const float* ea   = (const float*)d_in[2];
    const int*   batch= (const int*)  d_in[3];
    const float* l0ew = (const float*)d_in[4];
    const float* l0eb = (const float*)d_in[5];
    const float* l0w1 = (const float*)d_in[6];
    const float* l0b1 = (const float*)d_in[7];
    const float* l0w2 = (const float*)d_in[8];
    const float* l0b2 = (const float*)d_in[9];
    const float* ewA  = (const float*)d_in[10];  // [3, H, DE]
    const float* ebA  = (const float*)d_in[11];  // [3, H]
    const float* w1A  = (const float*)d_in[12];  // [3, H, H]
    const float* b1A  = (const float*)d_in[13];
    const float* w2A  = (const float*)d_in[14];
    const float* b2A  = (const float*)d_in[15];
    const float* bng  = (const float*)d_in[16];  // [4, H]
    const float* bnb  = (const float*)d_in[17];
    const float* hw1  = (const float*)d_in[18];
    const float* hb1  = (const float*)d_in[19];
    const float* hw2  = (const float*)d_in[20];
    const float* hb2  = (const float*)d_in[21];
    float* out = (float*)d_out;

    const int ZB = cN * cH / 4 / 256;  // 6250
    const int NB = (cN + 31) / 32;     // 3125
    const int EB = 4096;
    const int MB = cN * 16 / 256;      // 6250

    // layer 0 (CIN = 32)
    zero_kernel<<<ZB, 256>>>();
    edge_kernel<cDIN><<<EB, 256>>>(x, 0, ei, ea, l0ew, l0eb);
    node_kernel<cDIN><<<NB, 256>>>(x, 0, l0w1, l0b1, l0w2, l0b2);
    norm_kernel<<<MB, 256>>>(bng, bnb, batch, 0);

    // layers 1..3 (CIN = 64)
    for (int i = 0; i < 3; i++) {
        int last = (i == 2) ? 1 : 0;
        zero_kernel<<<ZB, 256>>>();
        edge_kernel<cH><<<EB, 256>>>(nullptr, 1, ei, ea,
                                     ewA + (size_t)i * cH * cDE, ebA + (size_t)i * cH);
        node_kernel<cH><<<NB, 256>>>(nullptr, 1,
                                     w1A + (size_t)i * cH * cH, b1A + (size_t)i * cH,
                                     w2A + (size_t)i * cH * cH, b2A + (size_t)i * cH);
        norm_kernel<<<MB, 256>>>(bng + (size_t)(i + 1) * cH,
                                 bnb + (size_t)(i + 1) * cH, batch, last);
    }

    head_kernel<<<cG, 128>>>(hw1, hb1, hw2, hb2, out);
}

// round 2
// speedup vs baseline: 1.3006x; 1.3006x over previous
#include <cuda_runtime.h>

#define DEV_INLINE __device__ __forceinline__

constexpr int cN   = 100000;   // nodes
constexpr int cE   = 1600000;  // edges
constexpr int cDIN = 32;       // node in channels
constexpr int cDE  = 16;       // edge feature dim
constexpr int cH   = 64;       // hidden
constexpr int cMH  = 128;      // mlp hidden
constexpr int cOUT = 10;       // out channels
constexpr int cG   = 128;      // graphs

// ---------------- scratch (device globals; no allocation allowed) ----------
__device__ __align__(16) float g_u[cN * cH];     // x + agg (node MLP input)
__device__ __align__(16) float g_h[cN * cH];     // node MLP output (pre-BN)
__device__ __align__(16) float g_x[cN * cH];     // post-BN activations
__device__ __align__(16) int   g_deg[cN];
__device__ __align__(16) int   g_woff[cN];
__device__ __align__(16) int   g_rowptr[cN + 1];
__device__ __align__(16) int2  g_se[cE];         // (src, edge_id) sorted by dst
__device__ __align__(16) float g_sum[cH];
__device__ __align__(16) float g_sumsq[cH];
__device__ __align__(16) float g_pool[cG * cH];
__device__ __align__(16) int   g_cnt[cG];

DEV_INLINE void red_add_v4(float* p, float a, float b, float c, float d) {
    asm volatile("red.global.add.v4.f32 [%0], {%1,%2,%3,%4};"
                 :: "l"(p), "f"(a), "f"(b), "f"(c), "f"(d) : "memory");
}

typedef unsigned long long ull;
DEV_INLINE ull ffma2(ull a, ull b, ull c) {
    ull d;
    asm("fma.rn.f32x2 %0, %1, %2, %3;" : "=l"(d) : "l"(a), "l"(b), "l"(c));
    return d;
}
DEV_INLINE ull pack2(float lo, float hi) {
    ull v;
    asm("mov.b64 %0, {%1, %2};" : "=l"(v) : "f"(lo), "f"(hi));
    return v;
}
DEV_INLINE float2 unpack2(ull v) {
    float2 f;
    asm("mov.b64 {%0, %1}, %2;" : "=f"(f.x), "=f"(f.y) : "l"(v));
    return f;
}

// ---------------- CSR build -------------------------------------------------
__global__ void __launch_bounds__(256) init_kernel() {
    int i = blockIdx.x * 256 + threadIdx.x;
    if (i < cN) g_deg[i] = 0;
    if (i < cG * cH) g_pool[i] = 0.f;
    if (i < cG) g_cnt[i] = 0;
    if (i < cH) { g_sum[i] = 0.f; g_sumsq[i] = 0.f; }
}

__global__ void __launch_bounds__(256) hist_kernel(const int* __restrict__ ei) {
    int e = blockIdx.x * 256 + threadIdx.x;
    if (e < cE) atomicAdd(&g_deg[ei[cE + e]], 1);
}

__global__ void __launch_bounds__(1024) scan_kernel() {
    const int TP = (cN + 1023) / 1024;  // 98
    int t = threadIdx.x;
    int s0 = t * TP, s1 = min(s0 + TP, cN);
    int ls = 0;
    for (int i = s0; i < s1; i++) ls += g_deg[i];
    __shared__ int ps[1024];
    ps[t] = ls;
    __syncthreads();
    for (int off = 1; off < 1024; off <<= 1) {
        int v = (t >= off) ? ps[t - off] : 0;
        __syncthreads();
        ps[t] += v;
        __syncthreads();
    }
    int run = ps[t] - ls;
    for (int i = s0; i < s1; i++) {
        g_rowptr[i] = run;
        g_woff[i]   = run;
        run += g_deg[i];
    }
    if (t == 0) g_rowptr[cN] = cE;
}

__global__ void __launch_bounds__(256) scatter_kernel(const int* __restrict__ ei) {
    int e = blockIdx.x * 256 + threadIdx.x;
    if (e >= cE) return;
    int d = ei[cE + e];
    int pos = atomicAdd(&g_woff[d], 1);
    g_se[pos] = make_int2(ei[e], e);
}

// ---------------- edge message + gather aggregate --------------------------
// u[d] = x[d] + sum_{e: dst=d} relu(x[src_e] + ea_e @ ew^T + eb)
// 16 threads per dst node, CPT = C/16 channels each. Weights in registers,
// packed (k,k+1) pairs for fma.rn.f32x2.
template <int C>
__global__ void __launch_bounds__(256) gather_kernel(
    const float* __restrict__ xin, int use_internal,
    const float* __restrict__ ea,
    const float* __restrict__ ew, const float* __restrict__ eb)
{
    constexpr int CPT = C / 16;  // 2 (layer0) or 4
    constexpr int KP  = cDE / 2; // 8 k-pairs

    __shared__ float ew_s[C * cDE];
    __shared__ float eb_s[C];

    const float* x = use_internal ? g_x : xin;
    int t = threadIdx.x;

    if (blockIdx.x == 0 && t < cH) { g_sum[t] = 0.f; g_sumsq[t] = 0.f; }
    for (int i = t; i < C * cDE; i += 256) ew_s[i] = ew[i];
    if (t < C) eb_s[t] = eb[t];
    __syncthreads();

    int l = t & 15;
    int c0 = l * CPT;

    ull wreg[CPT][KP];
    #pragma unroll
    for (int c = 0; c < CPT; c++)
        #pragma unroll
        for (int j = 0; j < KP; j++)
            wreg[c][j] = *(const ull*)&ew_s[(c0 + c) * cDE + 2 * j];
    ull ebreg[CPT];
    #pragma unroll
    for (int c = 0; c < CPT; c++) ebreg[c] = pack2(eb_s[c0 + c], 0.f);

    int node = blockIdx.x * 16 + (t >> 4);
    if (node >= cN) return;
    int es = g_rowptr[node], ee = g_rowptr[node + 1];

    float acc[CPT];
    #pragma unroll
    for (int c = 0; c < CPT; c++) acc[c] = 0.f;

    for (int e = es; e < ee; e++) {
        int2 se = g_se[e];
        const float4* eap = (const float4*)(ea + (size_t)se.y * cDE);
        ull e2[KP];
        #pragma unroll
        for (int j = 0; j < 4; j++) {
            float4 v = eap[j];
            e2[2 * j]     = pack2(v.x, v.y);
            e2[2 * j + 1] = pack2(v.z, v.w);
        }
        float xv[CPT];
        if (CPT == 4) {
            float4 xx = *(const float4*)(x + (size_t)se.x * C + c0);
            xv[0] = xx.x; xv[1] = xx.y; xv[2] = xx.z; xv[3] = xx.w;
        } else {
            float2 xx = *(const float2*)(x + (size_t)se.x * C + c0);
            xv[0] = xx.x; xv[1] = xx.y;
        }
        #pragma unroll
        for (int c = 0; c < CPT; c++) {
            ull d2 = ebreg[c];
            #pragma unroll
            for (int j = 0; j < KP; j++) d2 = ffma2(wreg[c][j], e2[j], d2);
            float2 p = unpack2(d2);
            acc[c] += fmaxf(xv[c] + p.x + p.y, 0.f);
        }
    }

    // u = x[node] + agg
    if (CPT == 4) {
        float4 xx = *(const float4*)(x + (size_t)node * C + c0);
        *(float4*)(g_u + (size_t)node * C + c0) =
            make_float4(xx.x + acc[0], xx.y + acc[1], xx.z + acc[2], xx.w + acc[3]);
    } else {
        float2 xx = *(const float2*)(x + (size_t)node * C + c0);
        *(float2*)(g_u + (size_t)node * C + c0) = make_float2(xx.x + acc[0], xx.y + acc[1]);
    }
}

// ---------------- node update: h2 = relu(relu(u W1^T + b1) W2^T + b2) ------
// 32-node tile, 256 threads, 8 outputs/thread; f32x2 pairs along K.
template <int CIN>
__global__ void __launch_bounds__(256) node_kernel(
    const float* __restrict__ w1, const float* __restrict__ b1,
    const float* __restrict__ w2, const float* __restrict__ b2)
{
    constexpr int KP1 = CIN / 2;   // 16 or 32
    constexpr int US  = KP1 + 1;
    constexpr int KP2 = cH / 2;    // 32
    constexpr int HS  = KP2 + 1;   // 33

    __shared__ ull us2[32 * US];         // input tile (doubles = k-pairs)
    __shared__ ull w2s[cH * KP2];        // W1 then W2 (doubles)
    __shared__ ull hs2[32 * HS];         // h1 tile, then reused for h2

    int t = threadIdx.x;
    int n0 = blockIdx.x * 32;

    for (int i = t; i < 32 * KP1; i += 256) {
        int n = i / KP1, j = i % KP1;
        us2[n * US + j] = *(const ull*)&g_u[(size_t)(n0 + n) * CIN + 2 * j];
    }
    for (int i = t; i < cH * KP1; i += 256) w2s[i] = ((const ull*)w1)[i];
    __syncthreads();

    int n = t & 31, og = t >> 5;         // og in 0..7
    float* hsf = (float*)hs2;

    ull acc2[8];
    #pragma unroll
    for (int j = 0; j < 8; j++) acc2[j] = pack2(b1[og * 8 + j], 0.f);
    for (int kp = 0; kp < KP1; kp++) {
        ull u2 = us2[n * US + kp];
        #pragma unroll
        for (int j = 0; j < 8; j++)
            acc2[j] = ffma2(w2s[(og * 8 + j) * KP1 + kp], u2, acc2[j]);
    }
    #pragma unroll
    for (int j = 0; j < 8; j++) {
        float2 p = unpack2(acc2[j]);
        hsf[n * (2 * HS) + og * 8 + j] = fmaxf(p.x + p.y, 0.f);
    }
    __syncthreads();

    for (int i = t; i < cH * KP2; i += 256) w2s[i] = ((const ull*)w2)[i];
    __syncthreads();

    #pragma unroll
    for (int j = 0; j < 8; j++) acc2[j] = pack2(b2[og * 8 + j], 0.f);
    for (int kp = 0; kp < KP2; kp++) {
        ull h2 = hs2[n * HS + kp];
        #pragma unroll
        for (int j = 0; j < 8; j++)
            acc2[j] = ffma2(w2s[(og * 8 + j) * KP2 + kp], h2, acc2[j]);
    }
    float v[8];
    #pragma unroll
    for (int j = 0; j < 8; j++) {
        float2 p = unpack2(acc2[j]);
        v[j] = fmaxf(p.x + p.y, 0.f);
        g_h[(size_t)(n0 + n) * cH + og * 8 + j] = v[j];
    }
    __syncthreads();  // all reads of hs2 done; reuse for BN staging
    float* bnf = (float*)us2;
    #pragma unroll
    for (int j = 0; j < 8; j++) bnf[n * 66 + og * 8 + j] = v[j];
    __syncthreads();

    if (t < cH) {
        float s = 0.f, s2 = 0.f;
        for (int nn = 0; nn < 32; nn++) {
            float x = bnf[nn * 66 + t];
            s += x; s2 += x * x;
        }
        atomicAdd(&g_sum[t], s);
        atomicAdd(&g_sumsq[t], s2);
    }
}

// ---------------- BN normalize (+ relu), optionally fused graph pooling ----
__global__ void __launch_bounds__(256) norm_kernel(
    const float* __restrict__ gamma, const float* __restrict__ beta,
    const int* __restrict__ batch, int last)
{
    int idx = blockIdx.x * 256 + threadIdx.x;
    if (idx >= cN * 16) return;
    int node = idx >> 4;
    int c0 = (idx & 15) * 4;
    float4 h = ((const float4*)g_h)[idx];
    float v[4] = {h.x, h.y, h.z, h.w};
    #pragma unroll
    for (int j = 0; j < 4; j++) {
        int c = c0 + j;
        float mu  = g_sum[c]   * (1.f / cN);
        float var = g_sumsq[c] * (1.f / cN) - mu * mu;
        float sc  = rsqrtf(var + 1e-5f) * gamma[c];
        v[j] = fmaxf((v[j] - mu) * sc + beta[c], 0.f);
    }
    ((float4*)g_x)[idx] = make_float4(v[0], v[1], v[2], v[3]);
    if (last) {
        int b = batch[node];
        red_add_v4(&g_pool[b * cH + c0], v[0], v[1], v[2], v[3]);
        if (c0 == 0) atomicAdd(&g_cnt[b], 1);
    }
}

// ---------------- pooled mean + MLP head -----------------------------------
__global__ void __launch_bounds__(128) head_kernel(
    const float* __restrict__ hw1, const float* __restrict__ hb1,
    const float* __restrict__ hw2, const float* __restrict__ hb2,
    float* __restrict__ out)
{
    __shared__ float p[cH], z[cMH];
    int g = blockIdx.x, t = threadIdx.x;
    if (t < cH) p[t] = g_pool[g * cH + t] / fmaxf((float)g_cnt[g], 1.f);
    __syncthreads();
    float acc = hb1[t];
    for (int c = 0; c < cH; c++) acc += p[c] * hw1[t * cH + c];
    z[t] = fmaxf(acc, 0.f);
    __syncthreads();
    if (t < cOUT) {
        float a = hb2[t];
        for (int m = 0; m < cMH; m++) a += z[m] * hw2[t * cMH + m];
        out[g * cOUT + t] = a;
    }
}

// ---------------- launch ----------------------------------------------------
extern "C" void kernel_launch(void* const* d_in, const int* in_sizes, int n_in,
                              void* d_out, int out_size)
{
    const float* x    = (const float*)d_in[0];
    const int*   ei   = (const int*)  d_in[1];
    const float* ea   = (const float*)d_in[2];
    const int*   batch= (const int*)  d_in[3];
    const float* l0ew = (const float*)d_in[4];
    const float* l0eb = (const float*)d_in[5];
    const float* l0w1 = (const float*)d_in[6];
    const float* l0b1 = (const float*)d_in[7];
    const float* l0w2 = (const float*)d_in[8];
    const float* l0b2 = (const float*)d_in[9];
    const float* ewA  = (const float*)d_in[10];  // [3, H, DE]
    const float* ebA  = (const float*)d_in[11];  // [3, H]
    const float* w1A  = (const float*)d_in[12];  // [3, H, H]
    const float* b1A  = (const float*)d_in[13];
    const float* w2A  = (const float*)d_in[14];
    const float* b2A  = (const float*)d_in[15];
    const float* bng  = (const float*)d_in[16];  // [4, H]
    const float* bnb  = (const float*)d_in[17];
    const float* hw1  = (const float*)d_in[18];
    const float* hb1  = (const float*)d_in[19];
    const float* hw2  = (const float*)d_in[20];
    const float* hb2  = (const float*)d_in[21];
    float* out = (float*)d_out;

    const int EB = (cE + 255) / 256;   // 6250
    const int GB = cN / 16;            // 6250
    const int NB = cN / 32;            // 3125
    const int MB = cN * 16 / 256;      // 6250
    const int IB = (cN + 255) / 256;   // covers all init targets

    // CSR build (by dst)
    init_kernel<<<IB, 256>>>();
    hist_kernel<<<EB, 256>>>(ei);
    scan_kernel<<<1, 1024>>>();
    scatter_kernel<<<EB, 256>>>(ei);

    // layer 0 (CIN = 32)
    gather_kernel<cDIN><<<GB, 256>>>(x, 0, ea, l0ew, l0eb);
    node_kernel<cDIN><<<NB, 256>>>(l0w1, l0b1, l0w2, l0b2);
    norm_kernel<<<MB, 256>>>(bng, bnb, batch, 0);

    // layers 1..3 (CIN = 64)
    for (int i = 0; i < 3; i++) {
        int last = (i == 2) ? 1 : 0;
        gather_kernel<cH><<<GB, 256>>>(nullptr, 1, ea,
                                       ewA + (size_t)i * cH * cDE, ebA + (size_t)i * cH);
        node_kernel<cH><<<NB, 256>>>(w1A + (size_t)i * cH * cH, b1A + (size_t)i * cH,
                                     w2A + (size_t)i * cH * cH, b2A + (size_t)i * cH);
        norm_kernel<<<MB, 256>>>(bng + (size_t)(i + 1) * cH,
                                 bnb + (size_t)(i + 1) * cH, batch, last);
    }

    head_kernel<<<cG, 128>>>(hw1, hb1, hw2, hb2, out);
}

// round 3
// speedup vs baseline: 1.4306x; 1.1000x over previous
#include <cuda_runtime.h>

#define DEV_INLINE __device__ __forceinline__

constexpr int cN   = 100000;   // nodes
constexpr int cE   = 1600000;  // edges
constexpr int cDIN = 32;       // node in channels
constexpr int cDE  = 16;       // edge feature dim
constexpr int cH   = 64;       // hidden
constexpr int cMH  = 128;      // mlp hidden
constexpr int cOUT = 10;       // out channels
constexpr int cG   = 128;      // graphs

typedef unsigned long long ull;

// ---------------- scratch (device globals; no allocation allowed) ----------
__device__ __align__(16) float g_u[cN * cH];       // x + agg (node MLP input)
__device__ __align__(16) float g_h[cN * cH];       // node MLP output (pre-BN)
__device__ __align__(16) float g_x[cN * cH];       // post-BN activations
__device__ __align__(16) float g_ea_perm[(size_t)cE * cDE];  // ea in CSR order
__device__ __align__(16) int   g_src[cE];          // src in CSR order
__device__ __align__(16) int   g_deg[cN];
__device__ __align__(16) int   g_woff[cN];
__device__ __align__(16) int   g_rowptr[cN + 1];
__device__ __align__(16) float g_sum[cH];
__device__ __align__(16) float g_sumsq[cH];
__device__ __align__(16) float g_pool[cG * cH];
__device__ __align__(16) int   g_cnt[cG];

DEV_INLINE void red_add_v4(float* p, float a, float b, float c, float d) {
    asm volatile("red.global.add.v4.f32 [%0], {%1,%2,%3,%4};"
                 :: "l"(p), "f"(a), "f"(b), "f"(c), "f"(d) : "memory");
}
DEV_INLINE ull ffma2(ull a, ull b, ull c) {
    ull d;
    asm("fma.rn.f32x2 %0, %1, %2, %3;" : "=l"(d) : "l"(a), "l"(b), "l"(c));
    return d;
}
DEV_INLINE ull pack2(float lo, float hi) {
    ull v;
    asm("mov.b64 %0, {%1, %2};" : "=l"(v) : "f"(lo), "f"(hi));
    return v;
}
DEV_INLINE float2 unpack2(ull v) {
    float2 f;
    asm("mov.b64 {%0, %1}, %2;" : "=f"(f.x), "=f"(f.y) : "l"(v));
    return f;
}

// ---------------- init + CSR build -----------------------------------------
__global__ void __launch_bounds__(256) init_kernel() {
    int i = blockIdx.x * 256 + threadIdx.x;
    if (i < cN) g_deg[i] = 0;
    if (i < cG * cH) g_pool[i] = 0.f;
    if (i < cG) g_cnt[i] = 0;
    if (i < cH) { g_sum[i] = 0.f; g_sumsq[i] = 0.f; }
}

__global__ void __launch_bounds__(256) hist_kernel(const int* __restrict__ ei) {
    int e = blockIdx.x * 256 + threadIdx.x;
    if (e < cE) atomicAdd(&g_deg[ei[cE + e]], 1);
}

__global__ void __launch_bounds__(1024) scan_kernel() {
    const int TP = (cN + 1023) / 1024;  // 98
    int t = threadIdx.x;
    int s0 = t * TP, s1 = min(s0 + TP, cN);
    int ls = 0;
    for (int i = s0; i < s1; i++) ls += g_deg[i];
    __shared__ int ps[1024];
    ps[t] = ls;
    __syncthreads();
    for (int off = 1; off < 1024; off <<= 1) {
        int v = (t >= off) ? ps[t - off] : 0;
        __syncthreads();
        ps[t] += v;
        __syncthreads();
    }
    int run = ps[t] - ls;
    for (int i = s0; i < s1; i++) {
        g_rowptr[i] = run;
        g_woff[i]   = run;
        run += g_deg[i];
    }
    if (t == 0) g_rowptr[cN] = cE;
}

// scatter + permute edge_attr into CSR (dst-sorted) order, fused
__global__ void __launch_bounds__(256) scatter_kernel(
    const int* __restrict__ ei, const float* __restrict__ ea)
{
    int e = blockIdx.x * 256 + threadIdx.x;
    if (e >= cE) return;
    int s = ei[e], d = ei[cE + e];
    int pos = atomicAdd(&g_woff[d], 1);
    g_src[pos] = s;
    const float4* sp = (const float4*)(ea + (size_t)e * cDE);
    float4 a = sp[0], b = sp[1], c = sp[2], dd = sp[3];
    float4* dp = (float4*)(g_ea_perm + (size_t)pos * cDE);
    dp[0] = a; dp[1] = b; dp[2] = c; dp[3] = dd;
}

// ---------------- edge message + gather aggregate --------------------------
// u[d] = x[d] + sum_{e in CSR[d]} relu(x[src_e] + ea_e @ ew^T + eb)
// Warp per node (32 lanes, CPT = C/32 channels each). Edge data staged to
// smem coalesced per 8-node block; weights in registers (f32x2 pairs).
template <int C>
__global__ void __launch_bounds__(256) gather_kernel(
    const float* __restrict__ xin, int use_internal,
    const float* __restrict__ ew, const float* __restrict__ eb)
{
    constexpr int CPT   = C / 32;   // 1 (layer0) or 2
    constexpr int KP    = cDE / 2;  // 8 k-pairs
    constexpr int CHUNK = 256;

    __shared__ __align__(16) float ea_s[CHUNK * cDE];
    __shared__ int src_s[CHUNK];

    const float* x = use_internal ? g_x : xin;
    int t = threadIdx.x;

    if (blockIdx.x == 0 && t < cH) { g_sum[t] = 0.f; g_sumsq[t] = 0.f; }

    int lane = t & 31;
    int c0 = lane * CPT;

    ull wreg[CPT][KP];
    float ebr[CPT];
    #pragma unroll
    for (int c = 0; c < CPT; c++) {
        #pragma unroll
        for (int j = 0; j < KP; j++)
            wreg[c][j] = *(const ull*)&ew[(c0 + c) * cDE + 2 * j];
        ebr[c] = eb[c0 + c];
    }

    int n0 = blockIdx.x * 8;
    int node = n0 + (t >> 5);
    int es_blk = g_rowptr[n0], ee_blk = g_rowptr[n0 + 8];
    int es = g_rowptr[node], ee = g_rowptr[node + 1];

    float acc[CPT];
    #pragma unroll
    for (int c = 0; c < CPT; c++) acc[c] = 0.f;

    for (int base = es_blk; base < ee_blk; base += CHUNK) {
        int cnt = min(CHUNK, ee_blk - base);
        __syncthreads();
        for (int i = t; i < cnt * (cDE / 4); i += 256)
            ((float4*)ea_s)[i] = ((const float4*)g_ea_perm)[(size_t)base * 4 + i];
        for (int i = t; i < cnt; i += 256) src_s[i] = g_src[base + i];
        __syncthreads();

        int e0 = max(es, base), e1 = min(ee, base + cnt);
        for (int e = e0; e < e1; e++) {
            int idx = e - base;
            int s = src_s[idx];
            const ull* eap = (const ull*)&ea_s[idx * cDE];
            float xv[CPT];
            if (CPT == 2) {
                float2 xx = *(const float2*)(x + (size_t)s * C + c0);
                xv[0] = xx.x; xv[1] = xx.y;
            } else {
                xv[0] = x[(size_t)s * C + c0];
            }
            #pragma unroll
            for (int c = 0; c < CPT; c++) {
                ull d2 = pack2(ebr[c], 0.f);
                #pragma unroll
                for (int j = 0; j < KP; j++) d2 = ffma2(wreg[c][j], eap[j], d2);
                float2 p = unpack2(d2);
                acc[c] += fmaxf(xv[c] + p.x + p.y, 0.f);
            }
        }
    }

    if (CPT == 2) {
        float2 xx = *(const float2*)(x + (size_t)node * C + c0);
        *(float2*)(g_u + (size_t)node * C + c0) =
            make_float2(xx.x + acc[0], xx.y + acc[1]);
    } else {
        g_u[(size_t)node * C + c0] = x[(size_t)node * C + c0] + acc[0];
    }
}

// ---------------- node update: h2 = relu(relu(u W1^T + b1) W2^T + b2) ------
// 128-node tile, 256 threads. Warp w owns output channels [w*8, w*8+8);
// each lane handles nodes {lane, lane+32, lane+64, lane+96}. Weight LDS are
// warp-broadcast; u LDS conflict-free. BN partial stats via shfl reduce.
template <int CIN>
__global__ void __launch_bounds__(256, 2) node_kernel(
    const float* __restrict__ w1, const float* __restrict__ b1,
    const float* __restrict__ w2, const float* __restrict__ b2)
{
    constexpr int KP1 = CIN / 2;   // 16 or 32
    constexpr int US  = KP1 + 1;
    constexpr int KP2 = cH / 2;    // 32
    constexpr int HS  = KP2 + 1;   // 33
    constexpr int WS  = KP2 + 1;   // padded weight stride (covers both)

    extern __shared__ __align__(16) ull dyn[];
    ull* us2 = dyn;                    // [128 * US]
    ull* ws2 = us2 + 128 * US;         // [64 * WS]
    ull* hs2 = ws2 + 64 * WS;          // [128 * HS]
    float* hsf = (float*)hs2;

    int t = threadIdx.x;
    int lane = t & 31;
    int w = t >> 5;                    // warp id = output group
    int n0 = blockIdx.x * 128;

    // load u tile (zero-pad invalid nodes)
    for (int i = t; i < 128 * KP1; i += 256) {
        int n = i / KP1, j = i % KP1;
        us2[n * US + j] = (n0 + n < cN)
            ? *(const ull*)&g_u[(size_t)(n0 + n) * CIN + 2 * j] : 0ull;
    }
    for (int i = t; i < cH * KP1; i += 256) {
        int r = i / KP1, j = i % KP1;
        ws2[r * WS + j] = ((const ull*)w1)[i];
    }
    __syncthreads();

    // ---- GEMM 1 ----
    ull acc2[4][8];
    #pragma unroll
    for (int j = 0; j < 8; j++) {
        ull b = pack2(b1[w * 8 + j], 0.f);
        #pragma unroll
        for (int i = 0; i < 4; i++) acc2[i][j] = b;
    }
    for (int kp = 0; kp < KP1; kp++) {
        ull wt[8], uv[4];
        #pragma unroll
        for (int j = 0; j < 8; j++) wt[j] = ws2[(w * 8 + j) * WS + kp];
        #pragma unroll
        for (int i = 0; i < 4; i++) uv[i] = us2[(lane + 32 * i) * US + kp];
        #pragma unroll
        for (int i = 0; i < 4; i++)
            #pragma unroll
            for (int j = 0; j < 8; j++)
                acc2[i][j] = ffma2(wt[j], uv[i], acc2[i][j]);
    }
    #pragma unroll
    for (int i = 0; i < 4; i++) {
        int n = lane + 32 * i;
        #pragma unroll
        for (int j = 0; j < 8; j += 2) {
            float2 pa = unpack2(acc2[i][j]);
            float2 pb = unpack2(acc2[i][j + 1]);
            ull pk = pack2(fmaxf(pa.x + pa.y, 0.f), fmaxf(pb.x + pb.y, 0.f));
            *(ull*)&hsf[n * (2 * HS) + w * 8 + j] = pk;
        }
    }
    __syncthreads();

    for (int i = t; i < cH * KP2; i += 256) {
        int r = i / KP2, j = i % KP2;
        ws2[r * WS + j] = ((const ull*)w2)[i];
    }
    __syncthreads();

    // ---- GEMM 2 ----
    #pragma unroll
    for (int j = 0; j < 8; j++) {
        ull b = pack2(b2[w * 8 + j], 0.f);
        #pragma unroll
        for (int i = 0; i < 4; i++) acc2[i][j] = b;
    }
    for (int kp = 0; kp < KP2; kp++) {
        ull wt[8], uv[4];
        #pragma unroll
        for (int j = 0; j < 8; j++) wt[j] = ws2[(w * 8 + j) * WS + kp];
        #pragma unroll
        for (int i = 0; i < 4; i++) uv[i] = hs2[(lane + 32 * i) * HS + kp];
        #pragma unroll
        for (int i = 0; i < 4; i++)
            #pragma unroll
            for (int j = 0; j < 8; j++)
                acc2[i][j] = ffma2(wt[j], uv[i], acc2[i][j]);
    }

    float v[4][8];
    float s[8], q[8];
    #pragma unroll
    for (int j = 0; j < 8; j++) { s[j] = 0.f; q[j] = 0.f; }
    #pragma unroll
    for (int i = 0; i < 4; i++) {
        bool valid = (n0 + lane + 32 * i) < cN;
        #pragma unroll
        for (int j = 0; j < 8; j++) {
            float2 p = unpack2(acc2[i][j]);
            float vv = valid ? fmaxf(p.x + p.y, 0.f) : 0.f;
            v[i][j] = vv;
            s[j] += vv; q[j] += vv * vv;
        }
    }
    // BN partial sums: butterfly reduce within warp, lane 0 atomics
    #pragma unroll
    for (int j = 0; j < 8; j++) {
        #pragma unroll
        for (int off = 16; off > 0; off >>= 1) {
            s[j] += __shfl_xor_sync(0xffffffffu, s[j], off);
            q[j] += __shfl_xor_sync(0xffffffffu, q[j], off);
        }
    }
    if (lane == 0) {
        #pragma unroll
        for (int j = 0; j < 8; j++) {
            atomicAdd(&g_sum[w * 8 + j], s[j]);
            atomicAdd(&g_sumsq[w * 8 + j], q[j]);
        }
    }

    __syncthreads();  // all hs2 reads complete; reuse for h2 staging
    #pragma unroll
    for (int i = 0; i < 4; i++) {
        int n = lane + 32 * i;
        #pragma unroll
        for (int j = 0; j < 8; j += 2) {
            ull pk = pack2(v[i][j], v[i][j + 1]);
            *(ull*)&hsf[n * (2 * HS) + w * 8 + j] = pk;
        }
    }
    __syncthreads();
    // coalesced store of h2
    for (int i = t; i < 128 * cH / 2; i += 256) {
        int n = i / KP2, j = i % KP2;
        if (n0 + n < cN)
            *(ull*)&g_h[(size_t)(n0 + n) * cH + 2 * j] = *(ull*)&hsf[n * (2 * HS) + 2 * j];
    }
}

// ---------------- BN normalize (+ relu), optionally fused graph pooling ----
__global__ void __launch_bounds__(256) norm_kernel(
    const float* __restrict__ gamma, const float* __restrict__ beta,
    const int* __restrict__ batch, int last)
{
    int idx = blockIdx.x * 256 + threadIdx.x;
    if (idx >= cN * 16) return;
    int node = idx >> 4;
    int c0 = (idx & 15) * 4;
    float4 h = ((const float4*)g_h)[idx];
    float v[4] = {h.x, h.y, h.z, h.w};
    #pragma unroll
    for (int j = 0; j < 4; j++) {
        int c = c0 + j;
        float mu  = g_sum[c]   * (1.f / cN);
        float var = g_sumsq[c] * (1.f / cN) - mu * mu;
        float sc  = rsqrtf(var + 1e-5f) * gamma[c];
        v[j] = fmaxf((v[j] - mu) * sc + beta[c], 0.f);
    }
    ((float4*)g_x)[idx] = make_float4(v[0], v[1], v[2], v[3]);
    if (last) {
        int b = batch[node];
        red_add_v4(&g_pool[b * cH + c0], v[0], v[1], v[2], v[3]);
        if (c0 == 0) atomicAdd(&g_cnt[b], 1);
    }
}

// ---------------- pooled mean + MLP head -----------------------------------
__global__ void __launch_bounds__(128) head_kernel(
    const float* __restrict__ hw1, const float* __restrict__ hb1,
    const float* __restrict__ hw2, const float* __restrict__ hb2,
    float* __restrict__ out)
{
    __shared__ float p[cH], z[cMH];
    int g = blockIdx.x, t = threadIdx.x;
    if (t < cH) p[t] = g_pool[g * cH + t] / fmaxf((float)g_cnt[g], 1.f);
    __syncthreads();
    float acc = hb1[t];
    for (int c = 0; c < cH; c++) acc += p[c] * hw1[t * cH + c];
    z[t] = fmaxf(acc, 0.f);
    __syncthreads();
    if (t < cOUT) {
        float a = hb2[t];
        for (int m = 0; m < cMH; m++) a += z[m] * hw2[t * cMH + m];
        out[g * cOUT + t] = a;
    }
}

// ---------------- launch ----------------------------------------------------
extern "C" void kernel_launch(void* const* d_in, const int* in_sizes, int n_in,
                              void* d_out, int out_size)
{
    const float* x    = (const float*)d_in[0];
    const int*   ei   = (const int*)  d_in[1];
    const float* ea   = (const float*)d_in[2];
    const int*   batch= (const int*)  d_in[3];
    const float* l0ew = (const float*)d_in[4];
    const float* l0eb = (const float*)d_in[5];
    const float* l0w1 = (const float*)d_in[6];
    const float* l0b1 = (const float*)d_in[7];
    const float* l0w2 = (const float*)d_in[8];
    const float* l0b2 = (const float*)d_in[9];
    const float* ewA  = (const float*)d_in[10];  // [3, H, DE]
    const float* ebA  = (const float*)d_in[11];  // [3, H]
    const float* w1A  = (const float*)d_in[12];  // [3, H, H]
    const float* b1A  = (const float*)d_in[13];
    const float* w2A  = (const float*)d_in[14];
    const float* b2A  = (const float*)d_in[15];
    const float* bng  = (const float*)d_in[16];  // [4, H]
    const float* bnb  = (const float*)d_in[17];
    const float* hw1  = (const float*)d_in[18];
    const float* hb1  = (const float*)d_in[19];
    const float* hw2  = (const float*)d_in[20];
    const float* hb2  = (const float*)d_in[21];
    float* out = (float*)d_out;

    const int EB = (cE + 255) / 256;       // 6250
    const int GB = cN / 8;                 // 12500
    const int NB = (cN + 127) / 128;       // 782
    const int MB = cN * 16 / 256;          // 6250
    const int IB = (cN + 255) / 256;

    // dynamic smem sizes for node kernels
    const int SM32 = (128 * (cDIN / 2 + 1) + cH * 33 + 128 * 33) * 8;
    const int SM64 = (128 * (cH   / 2 + 1) + cH * 33 + 128 * 33) * 8;
    static bool attr_set = false;
    if (!attr_set) {
        cudaFuncSetAttribute(node_kernel<cDIN>,
                             cudaFuncAttributeMaxDynamicSharedMemorySize, SM32);
        cudaFuncSetAttribute(node_kernel<cH>,
                             cudaFuncAttributeMaxDynamicSharedMemorySize, SM64);
        attr_set = true;
    }

    // CSR build (by dst) + edge_attr permutation
    init_kernel<<<IB, 256>>>();
    hist_kernel<<<EB, 256>>>(ei);
    scan_kernel<<<1, 1024>>>();
    scatter_kernel<<<EB, 256>>>(ei, ea);

    // layer 0 (CIN = 32)
    gather_kernel<cDIN><<<GB, 256>>>(x, 0, l0ew, l0eb);
    node_kernel<cDIN><<<NB, 256, SM32>>>(l0w1, l0b1, l0w2, l0b2);
    norm_kernel<<<MB, 256>>>(bng, bnb, batch, 0);

    // layers 1..3 (CIN = 64)
    for (int i = 0; i < 3; i++) {
        int last = (i == 2) ? 1 : 0;
        gather_kernel<cH><<<GB, 256>>>(nullptr, 1,
                                       ewA + (size_t)i * cH * cDE, ebA + (size_t)i * cH);
        node_kernel<cH><<<NB, 256, SM64>>>(w1A + (size_t)i * cH * cH, b1A + (size_t)i * cH,
                                           w2A + (size_t)i * cH * cH, b2A + (size_t)i * cH);
        norm_kernel<<<MB, 256>>>(bng + (size_t)(i + 1) * cH,
                                 bnb + (size_t)(i + 1) * cH, batch, last);
    }

    head_kernel<<<cG, 128>>>(hw1, hb1, hw2, hb2, out);
}